// round 2
// baseline (speedup 1.0000x reference)
#include <cuda_runtime.h>

#define B_ 16
#define S_ 512
#define H_ 768
#define ENT 9
#define INNER 64
#define OUTD (ENT * INNER * 2)   /* 1152 */
#define NEG_INF_F 1000000000000.0f

// Scratch: rotated q and k, laid out [ (b*ENT+h) ][ s ][ d ] contiguously.
__device__ float g_q[B_ * ENT * S_ * INNER];
__device__ float g_k[B_ * ENT * S_ * INNER];

// ---------------------------------------------------------------------------
// Kernel A: proj = X @ W + b, fused interleaved RoPE, scatter into g_q / g_k.
// X: [8192, 768], W: [768, 1152]. 64x64 tiles, K-tile 16, 256 threads, 4x4/thread.
// ---------------------------------------------------------------------------
__global__ __launch_bounds__(256) void proj_rope_kernel(
    const float* __restrict__ X,
    const float* __restrict__ W,
    const float* __restrict__ bias)
{
    __shared__ float As[64][16];
    __shared__ float Bs[16][64];

    const int t  = threadIdx.x;
    const int tx = t & 15;        // 0..15 -> n micro-tile
    const int ty = t >> 4;        // 0..15 -> m micro-tile
    const int m0 = blockIdx.y * 64;
    const int n0 = blockIdx.x * 64;

    float acc[4][4] = {};

    const int a_row = t >> 2;           // 0..63
    const int a_k4  = (t & 3) << 2;     // 0,4,8,12
    const int b_kr  = t >> 4;           // 0..15
    const int b_n4  = (t & 15) << 2;    // 0..60

    for (int k0 = 0; k0 < H_; k0 += 16) {
        *(float4*)&As[a_row][a_k4] =
            *(const float4*)&X[(size_t)(m0 + a_row) * H_ + k0 + a_k4];
        *(float4*)&Bs[b_kr][b_n4] =
            *(const float4*)&W[(size_t)(k0 + b_kr) * OUTD + n0 + b_n4];
        __syncthreads();

        #pragma unroll
        for (int k = 0; k < 16; k++) {
            float4 bf = *(float4*)&Bs[k][tx << 2];
            float bb0 = bf.x, bb1 = bf.y, bb2 = bf.z, bb3 = bf.w;
            #pragma unroll
            for (int r = 0; r < 4; r++) {
                float a = As[(ty << 2) + r][k];
                acc[r][0] += a * bb0;
                acc[r][1] += a * bb1;
                acc[r][2] += a * bb2;
                acc[r][3] += a * bb3;
            }
        }
        __syncthreads();
    }

    // Epilogue: bias + RoPE + scatter. Pairs (2i,2i+1) are inside the 4-col group.
    #pragma unroll
    for (int r = 0; r < 4; r++) {
        const int m  = m0 + (ty << 2) + r;
        const int bb = m >> 9;          // batch
        const int s  = m & (S_ - 1);    // seq pos
        const float sf = (float)s;
        #pragma unroll
        for (int c = 0; c < 4; c += 2) {
            const int n   = n0 + (tx << 2) + c;
            const int ent = n >> 7;
            const int j   = n & 127;
            const int isK = (j >= INNER);
            const int d   = isK ? (j - INNER) : j;
            const int i   = d >> 1;
            const float inv = powf(10000.0f, -(float)i / 32.0f);
            float cs, sn;
            sincosf(sf * inv, &cs, &sn);
            const float x0 = acc[r][c]     + bias[n];
            const float x1 = acc[r][c + 1] + bias[n + 1];
            const float y0 = x0 * cs - x1 * sn;
            const float y1 = x1 * cs + x0 * sn;
            float* dst = isK ? g_k : g_q;
            const size_t base =
                (((size_t)(bb * ENT + ent)) * S_ + s) * INNER + d;
            dst[base]     = y0;
            dst[base + 1] = y1;
        }
    }
}

// ---------------------------------------------------------------------------
// Kernel B: logits[bh, m, n] = (q[bh,m,:] . k[bh,n,:]) * pad(n) - masks, / 8.
// 64x64 output tile per block, K=64 one shot. Smem tiles stored d-major so the
// inner loop is 2x LDS.128 per 16 FMA.
// ---------------------------------------------------------------------------
__global__ __launch_bounds__(256) void attn_logits_kernel(
    const float* __restrict__ amask,
    float* __restrict__ out)
{
    __shared__ float Qs[64][64];  // [d][m]
    __shared__ float Ks[64][64];  // [d][n]

    const int t  = threadIdx.x;
    const int tx = t & 15;
    const int ty = t >> 4;
    const int bh = blockIdx.z;        // b*ENT + h
    const int b  = bh / ENT;
    const int m0 = blockIdx.y * 64;
    const int n0 = blockIdx.x * 64;

    const float* qb = g_q + (size_t)bh * S_ * INNER;
    const float* kb = g_k + (size_t)bh * S_ * INNER;

    #pragma unroll
    for (int ch = 0; ch < 4; ch++) {
        const int lin = ch * 256 + t;
        const int row = lin >> 4;         // 0..63
        const int d4  = (lin & 15) << 2;  // 0..60
        float4 q4 = *(const float4*)&qb[(size_t)(m0 + row) * INNER + d4];
        Qs[d4 + 0][row] = q4.x;
        Qs[d4 + 1][row] = q4.y;
        Qs[d4 + 2][row] = q4.z;
        Qs[d4 + 3][row] = q4.w;
        float4 k4 = *(const float4*)&kb[(size_t)(n0 + row) * INNER + d4];
        Ks[d4 + 0][row] = k4.x;
        Ks[d4 + 1][row] = k4.y;
        Ks[d4 + 2][row] = k4.z;
        Ks[d4 + 3][row] = k4.w;
    }
    __syncthreads();

    float acc[4][4] = {};
    #pragma unroll
    for (int k = 0; k < 64; k++) {
        float4 qf = *(float4*)&Qs[k][ty << 2];
        float4 kf = *(float4*)&Ks[k][tx << 2];
        float qr[4] = {qf.x, qf.y, qf.z, qf.w};
        float kc[4] = {kf.x, kf.y, kf.z, kf.w};
        #pragma unroll
        for (int r = 0; r < 4; r++) {
            acc[r][0] += qr[r] * kc[0];
            acc[r][1] += qr[r] * kc[1];
            acc[r][2] += qr[r] * kc[2];
            acc[r][3] += qr[r] * kc[3];
        }
    }

    // Epilogue: pad mask (depends on n), strict-lower causal mask, scale 1/8.
    const int nbase = n0 + (tx << 2);
    float pad[4];
    #pragma unroll
    for (int c = 0; c < 4; c++) pad[c] = amask[b * S_ + nbase + c];

    #pragma unroll
    for (int r = 0; r < 4; r++) {
        const int m = m0 + (ty << 2) + r;
        float4 o;
        float v[4];
        #pragma unroll
        for (int c = 0; c < 4; c++) {
            const int n = nbase + c;
            float x = acc[r][c] * pad[c] - (1.0f - pad[c]) * NEG_INF_F;
            if (n < m) x -= NEG_INF_F;
            v[c] = x * 0.125f;
        }
        o.x = v[0]; o.y = v[1]; o.z = v[2]; o.w = v[3];
        *(float4*)&out[(((size_t)bh * S_) + m) * S_ + nbase] = o;
    }
}

// ---------------------------------------------------------------------------
extern "C" void kernel_launch(void* const* d_in, const int* in_sizes, int n_in,
                              void* d_out, int out_size)
{
    const float* X    = (const float*)d_in[0];  // last_hidden_state [16,512,768]
    const float* amsk = (const float*)d_in[1];  // attention_mask [16,512]
    const float* W    = (const float*)d_in[2];  // W_dense [768,1152]
    const float* bias = (const float*)d_in[3];  // b_dense [1152]
    float* out = (float*)d_out;                 // [16,9,512,512]

    (void)in_sizes; (void)n_in; (void)out_size;

    {
        dim3 grid(OUTD / 64, (B_ * S_) / 64);   // (18, 128)
        proj_rope_kernel<<<grid, 256>>>(X, W, bias);
    }
    {
        dim3 grid(S_ / 64, S_ / 64, B_ * ENT);  // (8, 8, 144)
        attn_logits_kernel<<<grid, 256>>>(amsk, out);
    }
}

// round 3
// speedup vs baseline: 3.0264x; 3.0264x over previous
#include <cuda_runtime.h>
#include <cuda_bf16.h>
#include <cstdint>

#define NEG_INF_F 1000000000000.0f

// ---------------- scratch (bf16 hi/lo splits) ----------------
__device__ __nv_bfloat16 g_Xh[8192 * 768];
__device__ __nv_bfloat16 g_Xl[8192 * 768];
__device__ __nv_bfloat16 g_Wh[768 * 1152];
__device__ __nv_bfloat16 g_Wl[768 * 1152];
__device__ __nv_bfloat16 g_qh[144 * 512 * 64];
__device__ __nv_bfloat16 g_ql[144 * 512 * 64];
__device__ __nv_bfloat16 g_kh[144 * 512 * 64];
__device__ __nv_bfloat16 g_kl[144 * 512 * 64];

// ---------------- PTX helpers ----------------
__device__ __forceinline__ uint32_t smem_u32(const void* p) {
    return (uint32_t)__cvta_generic_to_shared(p);
}
__device__ __forceinline__ void ldm_x4(uint32_t* r, uint32_t a) {
    asm volatile("ldmatrix.sync.aligned.m8n8.x4.shared.b16 {%0,%1,%2,%3}, [%4];"
                 : "=r"(r[0]), "=r"(r[1]), "=r"(r[2]), "=r"(r[3]) : "r"(a));
}
__device__ __forceinline__ void ldm_x4_t(uint32_t* r, uint32_t a) {
    asm volatile("ldmatrix.sync.aligned.m8n8.x4.trans.shared.b16 {%0,%1,%2,%3}, [%4];"
                 : "=r"(r[0]), "=r"(r[1]), "=r"(r[2]), "=r"(r[3]) : "r"(a));
}
__device__ __forceinline__ void mma_bf16(float* c, const uint32_t* a, const uint32_t* b) {
    asm volatile(
        "mma.sync.aligned.m16n8k16.row.col.f32.bf16.bf16.f32 "
        "{%0,%1,%2,%3}, {%4,%5,%6,%7}, {%8,%9}, {%0,%1,%2,%3};"
        : "+f"(c[0]), "+f"(c[1]), "+f"(c[2]), "+f"(c[3])
        : "r"(a[0]), "r"(a[1]), "r"(a[2]), "r"(a[3]), "r"(b[0]), "r"(b[1]));
}
__device__ __forceinline__ void split2(float x, __nv_bfloat16& h, __nv_bfloat16& l) {
    h = __float2bfloat16(x);
    l = __float2bfloat16(x - __bfloat162float(h));
}

// ---------------- split kernels ----------------
__global__ void split_X_kernel(const float* __restrict__ src) {
    const int n = 8192 * 768;
    for (int i = blockIdx.x * blockDim.x + threadIdx.x; i < n; i += gridDim.x * blockDim.x) {
        __nv_bfloat16 h, l;
        split2(src[i], h, l);
        g_Xh[i] = h; g_Xl[i] = l;
    }
}
__global__ void split_W_kernel(const float* __restrict__ src) {
    const int n = 768 * 1152;
    for (int i = blockIdx.x * blockDim.x + threadIdx.x; i < n; i += gridDim.x * blockDim.x) {
        __nv_bfloat16 h, l;
        split2(src[i], h, l);
        g_Wh[i] = h; g_Wl[i] = l;
    }
}

// ---------------- Kernel A: proj GEMM (bf16x3) + bias + RoPE -> q/k hi/lo ----------------
// M=8192, N=1152, K=768. Block tile 128x128, 8 warps (2x4), warp tile 64x32.
__global__ __launch_bounds__(256) void proj_mma_kernel(const float* __restrict__ bias)
{
    const int SA = 40, SB = 136;
    __shared__ __align__(16) __nv_bfloat16 Ah[128 * 40], Al[128 * 40];
    __shared__ __align__(16) __nv_bfloat16 Bh[32 * 136], Bl[32 * 136];

    const int t = threadIdx.x, lane = t & 31, wid = t >> 5;
    const int wm = wid >> 2, wn = wid & 3;
    const int g = lane >> 2, tg = lane & 3;
    const int qd = lane >> 3, rr8 = lane & 7;
    const int row_off = (qd & 1) * 8 + rr8;
    const int col_off = (qd >> 1) * 8;
    const int m0 = blockIdx.y * 128, n0 = blockIdx.x * 128;

    float c[4][4][4];
    #pragma unroll
    for (int i = 0; i < 4; i++)
        #pragma unroll
        for (int j = 0; j < 4; j++)
            #pragma unroll
            for (int k = 0; k < 4; k++) c[i][j][k] = 0.f;

    const uint32_t sAh = smem_u32(Ah), sAl = smem_u32(Al);
    const uint32_t sBh = smem_u32(Bh), sBl = smem_u32(Bl);

    for (int k0 = 0; k0 < 768; k0 += 32) {
        #pragma unroll
        for (int p = 0; p < 2; p++) {
            int lin = p * 256 + t;
            {   // A: 128 rows x 32 bf16 (4 uint4 chunks/row)
                int row = lin >> 2, c8 = (lin & 3) * 8;
                size_t src = (size_t)(m0 + row) * 768 + k0 + c8;
                *(uint4*)&Ah[row * SA + c8] = *(const uint4*)&g_Xh[src];
                *(uint4*)&Al[row * SA + c8] = *(const uint4*)&g_Xl[src];
            }
            {   // B: 32 rows x 128 bf16 (16 chunks/row)
                int row = lin >> 4, c8 = (lin & 15) * 8;
                size_t src = (size_t)(k0 + row) * 1152 + n0 + c8;
                *(uint4*)&Bh[row * SB + c8] = *(const uint4*)&g_Wh[src];
                *(uint4*)&Bl[row * SB + c8] = *(const uint4*)&g_Wl[src];
            }
        }
        __syncthreads();

        #pragma unroll
        for (int ks = 0; ks < 2; ks++) {
            uint32_t ah[4][4], al[4][4];
            #pragma unroll
            for (int mi = 0; mi < 4; mi++) {
                uint32_t off = ((wm * 64 + mi * 16 + row_off) * SA + ks * 16 + col_off) * 2;
                ldm_x4(ah[mi], sAh + off);
                ldm_x4(al[mi], sAl + off);
            }
            uint32_t bhf[4][2], blf[4][2];
            #pragma unroll
            for (int np = 0; np < 2; np++) {
                uint32_t off = ((ks * 16 + row_off) * SB + wn * 32 + np * 16 + col_off) * 2;
                uint32_t tmp[4];
                ldm_x4_t(tmp, sBh + off);
                bhf[2 * np][0] = tmp[0]; bhf[2 * np][1] = tmp[1];
                bhf[2 * np + 1][0] = tmp[2]; bhf[2 * np + 1][1] = tmp[3];
                ldm_x4_t(tmp, sBl + off);
                blf[2 * np][0] = tmp[0]; blf[2 * np][1] = tmp[1];
                blf[2 * np + 1][0] = tmp[2]; blf[2 * np + 1][1] = tmp[3];
            }
            #pragma unroll
            for (int mi = 0; mi < 4; mi++)
                #pragma unroll
                for (int ni = 0; ni < 4; ni++) {
                    mma_bf16(c[mi][ni], ah[mi], bhf[ni]);
                    mma_bf16(c[mi][ni], ah[mi], blf[ni]);
                    mma_bf16(c[mi][ni], al[mi], bhf[ni]);
                }
        }
        __syncthreads();
    }

    // Epilogue: bias + interleaved RoPE, scatter bf16 hi/lo into g_q*/g_k*.
    const float L2C = -13.287712379549449f / 32.0f;  // -log2(10000)/32
    #pragma unroll
    for (int mi = 0; mi < 4; mi++) {
        #pragma unroll
        for (int ni = 0; ni < 4; ni++) {
            const int row0 = m0 + wm * 64 + mi * 16 + g;
            const int n = n0 + wn * 32 + ni * 8 + 2 * tg;
            const int ent = n >> 7, j = n & 127;
            const int isK = j >> 6, d = j & 63, fi = d >> 1;
            const float inv = exp2f((float)fi * L2C);
            const float b0v = bias[n], b1v = bias[n + 1];
            const float x00 = c[mi][ni][0] + b0v, x01 = c[mi][ni][1] + b1v;
            const float x10 = c[mi][ni][2] + b0v, x11 = c[mi][ni][3] + b1v;
            const int bb = row0 >> 9, s0 = row0 & 511;
            float sn0, cs0, sn1, cs1;
            sincosf((float)s0 * inv, &sn0, &cs0);
            sincosf((float)(s0 + 8) * inv, &sn1, &cs1);
            const float y00 = x00 * cs0 - x01 * sn0, y01 = x01 * cs0 + x00 * sn0;
            const float y10 = x10 * cs1 - x11 * sn1, y11 = x11 * cs1 + x10 * sn1;
            __nv_bfloat16* ph = isK ? g_kh : g_qh;
            __nv_bfloat16* pl = isK ? g_kl : g_ql;
            const size_t base = (((size_t)(bb * 9 + ent)) * 512 + s0) * 64 + d;
            __nv_bfloat16 h0, l0, h1, l1;
            split2(y00, h0, l0); split2(y01, h1, l1);
            *(__nv_bfloat162*)&ph[base] = __halves2bfloat162(h0, h1);
            *(__nv_bfloat162*)&pl[base] = __halves2bfloat162(l0, l1);
            split2(y10, h0, l0); split2(y11, h1, l1);
            *(__nv_bfloat162*)&ph[base + 512] = __halves2bfloat162(h0, h1);
            *(__nv_bfloat162*)&pl[base + 512] = __halves2bfloat162(l0, l1);
        }
    }
}

// ---------------- Kernel B: QK^T (bf16x3) + masks ----------------
// Per (b,h): 512x512, K=64. Block 128x128, warp tile 64x32. Fully-masked tiles
// (strictly below diagonal) skip the MMA: |qk|/1e12 ~ 4e-11 rel.
__global__ __launch_bounds__(256) void attn_mma_kernel(const float* __restrict__ amask,
                                                       float* __restrict__ out)
{
    const int SA = 40;
    __shared__ __align__(16) __nv_bfloat16 Qh[128 * 40], Ql[128 * 40];
    __shared__ __align__(16) __nv_bfloat16 Kh[128 * 40], Kl[128 * 40];

    const int t = threadIdx.x, lane = t & 31, wid = t >> 5;
    const int wm = wid >> 2, wn = wid & 3;
    const int g = lane >> 2, tg = lane & 3;
    const int qd = lane >> 3, rr8 = lane & 7;
    const int row_off = (qd & 1) * 8 + rr8;
    const int col_off = (qd >> 1) * 8;

    const int tn = blockIdx.x, tm = blockIdx.y, bh = blockIdx.z;
    const int b = bh / 9;
    const int m0 = tm * 128, n0 = tn * 128;

    if (tn < tm) {  // fully causal-masked tile: write constant, skip MMA
        const int cg = (t & 31) * 4, rbase = t >> 5;
        float4 v;
        #pragma unroll
        for (int ci = 0; ci < 4; ci++) {
            float pad = amask[b * 512 + n0 + cg + ci];
            ((float*)&v)[ci] = (-(1.0f - pad) * NEG_INF_F - NEG_INF_F) * 0.125f;
        }
        #pragma unroll
        for (int rp = 0; rp < 16; rp++) {
            int m = m0 + rbase + rp * 8;
            *(float4*)&out[((size_t)bh * 512 + m) * 512 + n0 + cg] = v;
        }
        return;
    }

    const size_t qbase = (size_t)bh * 512 * 64;
    float c[4][4][4];
    #pragma unroll
    for (int i = 0; i < 4; i++)
        #pragma unroll
        for (int j = 0; j < 4; j++)
            #pragma unroll
            for (int k = 0; k < 4; k++) c[i][j][k] = 0.f;

    const uint32_t sQh = smem_u32(Qh), sQl = smem_u32(Ql);
    const uint32_t sKh = smem_u32(Kh), sKl = smem_u32(Kl);

    #pragma unroll
    for (int kt = 0; kt < 2; kt++) {
        const int k0 = kt * 32;
        #pragma unroll
        for (int p = 0; p < 2; p++) {
            int lin = p * 256 + t;
            int row = lin >> 2, c8 = (lin & 3) * 8;
            size_t sq = qbase + (size_t)(m0 + row) * 64 + k0 + c8;
            size_t sk = qbase + (size_t)(n0 + row) * 64 + k0 + c8;
            *(uint4*)&Qh[row * SA + c8] = *(const uint4*)&g_qh[sq];
            *(uint4*)&Ql[row * SA + c8] = *(const uint4*)&g_ql[sq];
            *(uint4*)&Kh[row * SA + c8] = *(const uint4*)&g_kh[sk];
            *(uint4*)&Kl[row * SA + c8] = *(const uint4*)&g_kl[sk];
        }
        __syncthreads();

        #pragma unroll
        for (int ks = 0; ks < 2; ks++) {
            uint32_t ah[4][4], al[4][4];
            #pragma unroll
            for (int mi = 0; mi < 4; mi++) {
                uint32_t off = ((wm * 64 + mi * 16 + row_off) * SA + ks * 16 + col_off) * 2;
                ldm_x4(ah[mi], sQh + off);
                ldm_x4(al[mi], sQl + off);
            }
            uint32_t bhf[4][2], blf[4][2];
            #pragma unroll
            for (int np = 0; np < 2; np++) {
                uint32_t off = ((wn * 32 + np * 16 + row_off) * SA + ks * 16 + col_off) * 2;
                uint32_t tmp[4];
                ldm_x4(tmp, sKh + off);
                bhf[2 * np][0] = tmp[0]; bhf[2 * np][1] = tmp[2];
                bhf[2 * np + 1][0] = tmp[1]; bhf[2 * np + 1][1] = tmp[3];
                ldm_x4(tmp, sKl + off);
                blf[2 * np][0] = tmp[0]; blf[2 * np][1] = tmp[2];
                blf[2 * np + 1][0] = tmp[1]; blf[2 * np + 1][1] = tmp[3];
            }
            #pragma unroll
            for (int mi = 0; mi < 4; mi++)
                #pragma unroll
                for (int ni = 0; ni < 4; ni++) {
                    mma_bf16(c[mi][ni], ah[mi], bhf[ni]);
                    mma_bf16(c[mi][ni], ah[mi], blf[ni]);
                    mma_bf16(c[mi][ni], al[mi], bhf[ni]);
                }
        }
        __syncthreads();
    }

    // Epilogue: pad mask, strict-lower causal, scale 1/8.
    #pragma unroll
    for (int mi = 0; mi < 4; mi++) {
        #pragma unroll
        for (int ni = 0; ni < 4; ni++) {
            const int row0 = m0 + wm * 64 + mi * 16 + g;
            const int row1 = row0 + 8;
            const int n = n0 + wn * 32 + ni * 8 + 2 * tg;
            const float pad0 = amask[b * 512 + n];
            const float pad1 = amask[b * 512 + n + 1];
            const float* cc = c[mi][ni];
            float v00 = cc[0] * pad0 - (1.f - pad0) * NEG_INF_F - (n     < row0 ? NEG_INF_F : 0.f);
            float v01 = cc[1] * pad1 - (1.f - pad1) * NEG_INF_F - (n + 1 < row0 ? NEG_INF_F : 0.f);
            float v10 = cc[2] * pad0 - (1.f - pad0) * NEG_INF_F - (n     < row1 ? NEG_INF_F : 0.f);
            float v11 = cc[3] * pad1 - (1.f - pad1) * NEG_INF_F - (n + 1 < row1 ? NEG_INF_F : 0.f);
            float2 o0 = {v00 * 0.125f, v01 * 0.125f};
            float2 o1 = {v10 * 0.125f, v11 * 0.125f};
            *(float2*)&out[((size_t)bh * 512 + row0) * 512 + n] = o0;
            *(float2*)&out[((size_t)bh * 512 + row1) * 512 + n] = o1;
        }
    }
}

// ---------------- launch ----------------
extern "C" void kernel_launch(void* const* d_in, const int* in_sizes, int n_in,
                              void* d_out, int out_size)
{
    const float* X    = (const float*)d_in[0];
    const float* amsk = (const float*)d_in[1];
    const float* W    = (const float*)d_in[2];
    const float* bias = (const float*)d_in[3];
    float* out = (float*)d_out;
    (void)in_sizes; (void)n_in; (void)out_size;

    split_X_kernel<<<2048, 256>>>(X);
    split_W_kernel<<<512, 256>>>(W);
    {
        dim3 grid(9, 64);        // N/128, M/128
        proj_mma_kernel<<<grid, 256>>>(bias);
    }
    {
        dim3 grid(4, 4, 144);    // n-tiles, m-tiles, b*h
        attn_mma_kernel<<<grid, 256>>>(amsk, out);
    }
}

// round 4
// speedup vs baseline: 5.5836x; 1.8450x over previous
#include <cuda_runtime.h>
#include <cuda_bf16.h>
#include <cstdint>

#define NEG_INF_F 1000000000000.0f

// ---------------- scratch (bf16) ----------------
__device__ __nv_bfloat16 g_Xb[8192 * 768];
__device__ __nv_bfloat16 g_Wb[768 * 1152];
__device__ __nv_bfloat16 g_qb[144 * 512 * 64];
__device__ __nv_bfloat16 g_kb[144 * 512 * 64];

// ---------------- PTX helpers ----------------
__device__ __forceinline__ uint32_t smem_u32(const void* p) {
    return (uint32_t)__cvta_generic_to_shared(p);
}
__device__ __forceinline__ void ldm_x4(uint32_t* r, uint32_t a) {
    asm volatile("ldmatrix.sync.aligned.m8n8.x4.shared.b16 {%0,%1,%2,%3}, [%4];"
                 : "=r"(r[0]), "=r"(r[1]), "=r"(r[2]), "=r"(r[3]) : "r"(a));
}
__device__ __forceinline__ void ldm_x4_t(uint32_t* r, uint32_t a) {
    asm volatile("ldmatrix.sync.aligned.m8n8.x4.trans.shared.b16 {%0,%1,%2,%3}, [%4];"
                 : "=r"(r[0]), "=r"(r[1]), "=r"(r[2]), "=r"(r[3]) : "r"(a));
}
__device__ __forceinline__ void mma_bf16(float* c, const uint32_t* a, const uint32_t* b) {
    asm volatile(
        "mma.sync.aligned.m16n8k16.row.col.f32.bf16.bf16.f32 "
        "{%0,%1,%2,%3}, {%4,%5,%6,%7}, {%8,%9}, {%0,%1,%2,%3};"
        : "+f"(c[0]), "+f"(c[1]), "+f"(c[2]), "+f"(c[3])
        : "r"(a[0]), "r"(a[1]), "r"(a[2]), "r"(a[3]), "r"(b[0]), "r"(b[1]));
}
#define CP_ASYNC16(dst, src) \
    asm volatile("cp.async.cg.shared.global [%0], [%1], 16;" :: "r"(dst), "l"(src))
#define CP_COMMIT() asm volatile("cp.async.commit_group;")
#define CP_WAIT(N)  asm volatile("cp.async.wait_group %0;" :: "n"(N))

// ---------------- convert kernels (f32 -> bf16) ----------------
__global__ void conv_X_kernel(const float* __restrict__ src) {
    const int n4 = 8192 * 768 / 4;
    for (int i = blockIdx.x * blockDim.x + threadIdx.x; i < n4; i += gridDim.x * blockDim.x) {
        float4 v = ((const float4*)src)[i];
        __nv_bfloat162 lo = __floats2bfloat162_rn(v.x, v.y);
        __nv_bfloat162 hi = __floats2bfloat162_rn(v.z, v.w);
        ((__nv_bfloat162*)g_Xb)[2 * i]     = lo;
        ((__nv_bfloat162*)g_Xb)[2 * i + 1] = hi;
    }
}
__global__ void conv_W_kernel(const float* __restrict__ src) {
    const int n4 = 768 * 1152 / 4;
    for (int i = blockIdx.x * blockDim.x + threadIdx.x; i < n4; i += gridDim.x * blockDim.x) {
        float4 v = ((const float4*)src)[i];
        __nv_bfloat162 lo = __floats2bfloat162_rn(v.x, v.y);
        __nv_bfloat162 hi = __floats2bfloat162_rn(v.z, v.w);
        ((__nv_bfloat162*)g_Wb)[2 * i]     = lo;
        ((__nv_bfloat162*)g_Wb)[2 * i + 1] = hi;
    }
}

// ---------------- Kernel A: proj GEMM (bf16) + bias + RoPE -> q/k bf16 ----------------
// M=8192, N=1152, K=768. Block tile 128x128, 8 warps (2x4), warp tile 64x32.
// cp.async 2-stage pipeline over K (24 tiles of 32).
__global__ __launch_bounds__(256) void proj_mma_kernel(const float* __restrict__ bias)
{
    const int SA = 40, SB = 136;
    __shared__ __align__(16) __nv_bfloat16 As[2][128 * 40];
    __shared__ __align__(16) __nv_bfloat16 Bs[2][32 * 136];

    const int t = threadIdx.x, lane = t & 31, wid = t >> 5;
    const int wm = wid >> 2, wn = wid & 3;
    const int g = lane >> 2, tg = lane & 3;
    const int qd = lane >> 3, rr8 = lane & 7;
    const int row_off = (qd & 1) * 8 + rr8;
    const int col_off = (qd >> 1) * 8;
    const int m0 = blockIdx.y * 128, n0 = blockIdx.x * 128;

    // cp.async source/dest coords (per thread: 2 chunks A, 2 chunks B)
    const int a_row0 = t >> 1,             a_c8_0 = (t & 1) * 16;      // rows 0..127, cols {0,16}
    const int b_row0 = t >> 4,             b_c8_0 = (t & 15) * 8;      // rows 0..15
    // second B half: rows 16..31
    float c[4][4][4];
    #pragma unroll
    for (int i = 0; i < 4; i++)
        #pragma unroll
        for (int j = 0; j < 4; j++)
            #pragma unroll
            for (int k = 0; k < 4; k++) c[i][j][k] = 0.f;

    const uint32_t sA0 = smem_u32(As[0]), sA1 = smem_u32(As[1]);
    const uint32_t sB0 = smem_u32(Bs[0]), sB1 = smem_u32(Bs[1]);

    auto issue_tile = [&](int k0, int buf) {
        uint32_t sa = buf ? sA1 : sA0, sb = buf ? sB1 : sB0;
        // A: 128x32 bf16; per-thread 2 x 16B
        {
            const __nv_bfloat16* src = &g_Xb[(size_t)(m0 + a_row0) * 768 + k0 + a_c8_0];
            CP_ASYNC16(sa + (a_row0 * SA + a_c8_0) * 2, src);
            const __nv_bfloat16* src2 = &g_Xb[(size_t)(m0 + a_row0) * 768 + k0 + a_c8_0 + 8];
            CP_ASYNC16(sa + (a_row0 * SA + a_c8_0 + 8) * 2, src2);
        }
        // B: 32x128 bf16; per-thread 2 x 16B (rows r and r+16)
        {
            const __nv_bfloat16* src = &g_Wb[(size_t)(k0 + b_row0) * 1152 + n0 + b_c8_0];
            CP_ASYNC16(sb + (b_row0 * SB + b_c8_0) * 2, src);
            const __nv_bfloat16* src2 = &g_Wb[(size_t)(k0 + b_row0 + 16) * 1152 + n0 + b_c8_0];
            CP_ASYNC16(sb + ((b_row0 + 16) * SB + b_c8_0) * 2, src2);
        }
        CP_COMMIT();
    };

    issue_tile(0, 0);

    const int NT = 24;
    for (int kt = 0; kt < NT; kt++) {
        if (kt + 1 < NT) {
            issue_tile((kt + 1) * 32, (kt + 1) & 1);
            CP_WAIT(1);
        } else {
            CP_WAIT(0);
        }
        __syncthreads();

        const uint32_t sa = (kt & 1) ? sA1 : sA0;
        const uint32_t sb = (kt & 1) ? sB1 : sB0;
        #pragma unroll
        for (int ks = 0; ks < 2; ks++) {
            uint32_t ah[4][4];
            #pragma unroll
            for (int mi = 0; mi < 4; mi++) {
                uint32_t off = ((wm * 64 + mi * 16 + row_off) * SA + ks * 16 + col_off) * 2;
                ldm_x4(ah[mi], sa + off);
            }
            uint32_t bhf[4][2];
            #pragma unroll
            for (int np = 0; np < 2; np++) {
                uint32_t off = ((ks * 16 + row_off) * SB + wn * 32 + np * 16 + col_off) * 2;
                uint32_t tmp[4];
                ldm_x4_t(tmp, sb + off);
                bhf[2 * np][0] = tmp[0]; bhf[2 * np][1] = tmp[1];
                bhf[2 * np + 1][0] = tmp[2]; bhf[2 * np + 1][1] = tmp[3];
            }
            #pragma unroll
            for (int mi = 0; mi < 4; mi++)
                #pragma unroll
                for (int ni = 0; ni < 4; ni++)
                    mma_bf16(c[mi][ni], ah[mi], bhf[ni]);
        }
        __syncthreads();
    }

    // Epilogue: bias + interleaved RoPE -> bf16 q/k.
    const float L2C = -13.287712379549449f / 32.0f;  // -log2(10000)/32
    #pragma unroll
    for (int mi = 0; mi < 4; mi++) {
        #pragma unroll
        for (int ni = 0; ni < 4; ni++) {
            const int row0 = m0 + wm * 64 + mi * 16 + g;
            const int n = n0 + wn * 32 + ni * 8 + 2 * tg;
            const int ent = n >> 7, j = n & 127;
            const int isK = j >> 6, d = j & 63, fi = d >> 1;
            const float inv = exp2f((float)fi * L2C);
            const float b0v = bias[n], b1v = bias[n + 1];
            const float x00 = c[mi][ni][0] + b0v, x01 = c[mi][ni][1] + b1v;
            const float x10 = c[mi][ni][2] + b0v, x11 = c[mi][ni][3] + b1v;
            const int bb = row0 >> 9, s0 = row0 & 511;
            float sn0, cs0, sn1, cs1;
            sincosf((float)s0 * inv, &sn0, &cs0);
            sincosf((float)(s0 + 8) * inv, &sn1, &cs1);
            const float y00 = x00 * cs0 - x01 * sn0, y01 = x01 * cs0 + x00 * sn0;
            const float y10 = x10 * cs1 - x11 * sn1, y11 = x11 * cs1 + x10 * sn1;
            __nv_bfloat16* p = isK ? g_kb : g_qb;
            const size_t base = (((size_t)(bb * 9 + ent)) * 512 + s0) * 64 + d;
            *(__nv_bfloat162*)&p[base]       = __floats2bfloat162_rn(y00, y01);
            *(__nv_bfloat162*)&p[base + 512] = __floats2bfloat162_rn(y10, y11);
        }
    }
}

// ---------------- Kernel B: QK^T (bf16) + masks ----------------
// Per (b,h): 512x512, K=64 loaded in one shot. Block 128x128, warp tile 64x32.
__global__ __launch_bounds__(256) void attn_mma_kernel(const float* __restrict__ amask,
                                                       float* __restrict__ out)
{
    const int SA = 72;
    __shared__ __align__(16) __nv_bfloat16 Qs[128 * 72];
    __shared__ __align__(16) __nv_bfloat16 Ks[128 * 72];

    const int t = threadIdx.x, lane = t & 31, wid = t >> 5;
    const int wm = wid >> 2, wn = wid & 3;
    const int g = lane >> 2, tg = lane & 3;
    const int qd = lane >> 3, rr8 = lane & 7;
    const int row_off = (qd & 1) * 8 + rr8;
    const int col_off = (qd >> 1) * 8;

    const int tn = blockIdx.x, tm = blockIdx.y, bh = blockIdx.z;
    const int b = bh / 9;
    const int m0 = tm * 128, n0 = tn * 128;

    if (tn < tm) {  // fully causal-masked tile: constant output, no MMA
        const int cg = (t & 31) * 4, rbase = t >> 5;
        float4 v;
        #pragma unroll
        for (int ci = 0; ci < 4; ci++) {
            float pad = amask[b * 512 + n0 + cg + ci];
            ((float*)&v)[ci] = (-(1.0f - pad) * NEG_INF_F - NEG_INF_F) * 0.125f;
        }
        #pragma unroll
        for (int rp = 0; rp < 16; rp++) {
            int m = m0 + rbase + rp * 8;
            *(float4*)&out[((size_t)bh * 512 + m) * 512 + n0 + cg] = v;
        }
        return;
    }

    const size_t qbase = (size_t)bh * 512 * 64;
    // Load full 128x64 Q and K tiles (8 chunks of 8 bf16 per row).
    #pragma unroll
    for (int p = 0; p < 4; p++) {
        const int lin = p * 256 + t;
        const int row = lin >> 3, c8 = (lin & 7) * 8;
        *(uint4*)&Qs[row * SA + c8] = *(const uint4*)&g_qb[qbase + (size_t)(m0 + row) * 64 + c8];
        *(uint4*)&Ks[row * SA + c8] = *(const uint4*)&g_kb[qbase + (size_t)(n0 + row) * 64 + c8];
    }
    __syncthreads();

    float c[4][4][4];
    #pragma unroll
    for (int i = 0; i < 4; i++)
        #pragma unroll
        for (int j = 0; j < 4; j++)
            #pragma unroll
            for (int k = 0; k < 4; k++) c[i][j][k] = 0.f;

    const uint32_t sQ = smem_u32(Qs), sK = smem_u32(Ks);

    #pragma unroll
    for (int ks = 0; ks < 4; ks++) {
        uint32_t ah[4][4];
        #pragma unroll
        for (int mi = 0; mi < 4; mi++) {
            uint32_t off = ((wm * 64 + mi * 16 + row_off) * SA + ks * 16 + col_off) * 2;
            ldm_x4(ah[mi], sQ + off);
        }
        uint32_t bhf[4][2];
        #pragma unroll
        for (int np = 0; np < 2; np++) {
            uint32_t off = ((wn * 32 + np * 16 + row_off) * SA + ks * 16 + col_off) * 2;
            uint32_t tmp[4];
            ldm_x4(tmp, sK + off);
            bhf[2 * np][0] = tmp[0]; bhf[2 * np][1] = tmp[2];
            bhf[2 * np + 1][0] = tmp[1]; bhf[2 * np + 1][1] = tmp[3];
        }
        #pragma unroll
        for (int mi = 0; mi < 4; mi++)
            #pragma unroll
            for (int ni = 0; ni < 4; ni++)
                mma_bf16(c[mi][ni], ah[mi], bhf[ni]);
    }

    // Epilogue: pad mask, strict-lower causal, scale 1/8.
    #pragma unroll
    for (int mi = 0; mi < 4; mi++) {
        #pragma unroll
        for (int ni = 0; ni < 4; ni++) {
            const int row0 = m0 + wm * 64 + mi * 16 + g;
            const int row1 = row0 + 8;
            const int n = n0 + wn * 32 + ni * 8 + 2 * tg;
            const float pad0 = amask[b * 512 + n];
            const float pad1 = amask[b * 512 + n + 1];
            const float* cc = c[mi][ni];
            float v00 = cc[0] * pad0 - (1.f - pad0) * NEG_INF_F - (n     < row0 ? NEG_INF_F : 0.f);
            float v01 = cc[1] * pad1 - (1.f - pad1) * NEG_INF_F - (n + 1 < row0 ? NEG_INF_F : 0.f);
            float v10 = cc[2] * pad0 - (1.f - pad0) * NEG_INF_F - (n     < row1 ? NEG_INF_F : 0.f);
            float v11 = cc[3] * pad1 - (1.f - pad1) * NEG_INF_F - (n + 1 < row1 ? NEG_INF_F : 0.f);
            float2 o0 = {v00 * 0.125f, v01 * 0.125f};
            float2 o1 = {v10 * 0.125f, v11 * 0.125f};
            *(float2*)&out[((size_t)bh * 512 + row0) * 512 + n] = o0;
            *(float2*)&out[((size_t)bh * 512 + row1) * 512 + n] = o1;
        }
    }
}

// ---------------- launch ----------------
extern "C" void kernel_launch(void* const* d_in, const int* in_sizes, int n_in,
                              void* d_out, int out_size)
{
    const float* X    = (const float*)d_in[0];
    const float* amsk = (const float*)d_in[1];
    const float* W    = (const float*)d_in[2];
    const float* bias = (const float*)d_in[3];
    float* out = (float*)d_out;
    (void)in_sizes; (void)n_in; (void)out_size;

    conv_X_kernel<<<1024, 256>>>(X);
    conv_W_kernel<<<256, 256>>>(W);
    {
        dim3 grid(9, 64);        // N/128, M/128
        proj_mma_kernel<<<grid, 256>>>(bias);
    }
    {
        dim3 grid(4, 4, 144);    // n-tiles, m-tiles, b*h
        attn_mma_kernel<<<grid, 256>>>(amsk, out);
    }
}

// round 7
// speedup vs baseline: 6.6376x; 1.1888x over previous
#include <cuda_runtime.h>
#include <cuda_bf16.h>
#include <cstdint>

#define NEG_INF_F 1000000000000.0f
#define W_SCALE 16.0f
#define INV_W_SCALE 0.0625f

// ---------------- scratch (fp8 e4m3) ----------------
__device__ uint8_t g_X8[8192 * 768];    // X e4m3 [m][k]
__device__ uint8_t g_Wt8[1152 * 768];   // (16*W)^T e4m3 [n][k]
__device__ uint8_t g_q8[144 * 512 * 64];
__device__ uint8_t g_k8[144 * 512 * 64];

// ---------------- PTX helpers ----------------
__device__ __forceinline__ uint32_t smem_u32(const void* p) {
    return (uint32_t)__cvta_generic_to_shared(p);
}
__device__ __forceinline__ void ldm_x4(uint32_t* r, uint32_t a) {
    asm volatile("ldmatrix.sync.aligned.m8n8.x4.shared.b16 {%0,%1,%2,%3}, [%4];"
                 : "=r"(r[0]), "=r"(r[1]), "=r"(r[2]), "=r"(r[3]) : "r"(a));
}
__device__ __forceinline__ void mma_fp8(float* c, const uint32_t* a, const uint32_t* b) {
    asm volatile(
        "mma.sync.aligned.m16n8k32.row.col.f32.e4m3.e4m3.f32 "
        "{%0,%1,%2,%3}, {%4,%5,%6,%7}, {%8,%9}, {%0,%1,%2,%3};"
        : "+f"(c[0]), "+f"(c[1]), "+f"(c[2]), "+f"(c[3])
        : "r"(a[0]), "r"(a[1]), "r"(a[2]), "r"(a[3]), "r"(b[0]), "r"(b[1]));
}
// d = (cvt(hi)<<8) | cvt(lo)
__device__ __forceinline__ uint16_t pack_e4m3x2(float hi, float lo) {
    uint16_t r;
    asm("cvt.rn.satfinite.e4m3x2.f32 %0, %1, %2;" : "=h"(r) : "f"(hi), "f"(lo));
    return r;
}
#define CP_ASYNC16(dst, src) \
    asm volatile("cp.async.cg.shared.global [%0], [%1], 16;" :: "r"(dst), "l"(src))
#define CP_COMMIT() asm volatile("cp.async.commit_group;")
#define CP_WAIT(N)  asm volatile("cp.async.wait_group %0;" :: "n"(N))

// ---------------- convert kernels ----------------
__global__ void conv_X_kernel(const float* __restrict__ src) {
    const int n4 = 8192 * 768 / 4;
    for (int i = blockIdx.x * blockDim.x + threadIdx.x; i < n4; i += gridDim.x * blockDim.x) {
        float4 v = ((const float4*)src)[i];
        uint16_t lo = pack_e4m3x2(v.y, v.x);
        uint16_t hi = pack_e4m3x2(v.w, v.z);
        ((uint32_t*)g_X8)[i] = ((uint32_t)hi << 16) | lo;
    }
}
// W [768][1152] f32 -> g_Wt8 [1152][768] e4m3 of 16*W
__global__ __launch_bounds__(256) void conv_WT_kernel(const float* __restrict__ W) {
    __shared__ float tile[32][33];
    const int n0 = blockIdx.x * 32, k0 = blockIdx.y * 32;
    const int tx = threadIdx.x & 31, ty = threadIdx.x >> 5;  // ty 0..7
    #pragma unroll
    for (int i = 0; i < 4; i++)
        tile[ty + 8 * i][tx] = W[(size_t)(k0 + ty + 8 * i) * 1152 + n0 + tx];
    __syncthreads();
    // write 2 bytes per op: threads cover (n, k-pair)
    const int kp = tx;  // 0..31 -> k pair index? need 16 pairs per row; remap:
    (void)kp;
    #pragma unroll
    for (int i = 0; i < 4; i++) {
        const int n = ty + 8 * i;          // local n row 0..31
        // each of 32 tx covers 1 element; store bytes individually (simple, tiny kernel)
        float v = tile[tx][n] * W_SCALE;
        uint16_t p = pack_e4m3x2(0.0f, v);
        g_Wt8[(size_t)(n0 + n) * 768 + k0 + tx] = (uint8_t)(p & 0xFF);
    }
}

// ---------------- Kernel A: proj GEMM (fp8 mma.sync) + bias + RoPE ----------------
// M=8192, N=1152, K=768. Block tile 128x128, 8 warps (2m x 4n), warp tile 64x32.
// K-tiles of 64 bytes, cp.async double buffer. smem rows padded to 80B.
__global__ __launch_bounds__(256, 2) void proj_mma_kernel(const float* __restrict__ bias)
{
    const int S = 80;
    __shared__ __align__(16) uint8_t As[2][128 * 80];
    __shared__ __align__(16) uint8_t Bs[2][128 * 80];

    const int t = threadIdx.x, lane = t & 31, wid = t >> 5;
    const int wm = wid >> 2, wn = wid & 3;
    const int g = lane >> 2, tg = lane & 3;
    const int qd = lane >> 3, rr8 = lane & 7;
    const int m0 = blockIdx.y * 128, n0 = blockIdx.x * 128;

    // fragment smem offsets (bytes)
    const int a_r = (qd & 1) * 8 + rr8, a_c = (qd >> 1) * 16;   // A matrices
    const int b_r = (qd >> 1) * 8 + rr8, b_c = (qd & 1) * 16;   // B matrices

    float c[4][4][4];
    #pragma unroll
    for (int i = 0; i < 4; i++)
        #pragma unroll
        for (int j = 0; j < 4; j++)
            #pragma unroll
            for (int k = 0; k < 4; k++) c[i][j][k] = 0.f;

    const uint32_t sA[2] = {smem_u32(As[0]), smem_u32(As[1])};
    const uint32_t sB[2] = {smem_u32(Bs[0]), smem_u32(Bs[1])};

    // fill one K-tile (64 bytes of k) into buf: A 128x64B, B 128x64B
    auto fill = [&](int buf, int k0) {
        #pragma unroll
        for (int j = 0; j < 2; j++) {
            const int idx = j * 256 + t;
            const int row = idx >> 2, cc = (idx & 3) * 16;
            CP_ASYNC16(sA[buf] + row * S + cc, &g_X8[(size_t)(m0 + row) * 768 + k0 + cc]);
            CP_ASYNC16(sB[buf] + row * S + cc, &g_Wt8[(size_t)(n0 + row) * 768 + k0 + cc]);
        }
        CP_COMMIT();
    };

    fill(0, 0);
    const int NT = 12;
    for (int kt = 0; kt < NT; kt++) {
        if (kt + 1 < NT) {
            fill((kt + 1) & 1, (kt + 1) * 64);
            CP_WAIT(1);
        } else {
            CP_WAIT(0);
        }
        __syncthreads();
        const uint32_t sa = sA[kt & 1], sb = sB[kt & 1];

        #pragma unroll
        for (int ks = 0; ks < 2; ks++) {
            uint32_t af[4][4];
            #pragma unroll
            for (int mi = 0; mi < 4; mi++)
                ldm_x4(af[mi], sa + (wm * 64 + mi * 16 + a_r) * S + ks * 32 + a_c);
            uint32_t bf[4][2];
            #pragma unroll
            for (int np = 0; np < 2; np++) {
                uint32_t tmp[4];
                ldm_x4(tmp, sb + (wn * 32 + np * 16 + b_r) * S + ks * 32 + b_c);
                bf[2 * np][0] = tmp[0]; bf[2 * np][1] = tmp[1];
                bf[2 * np + 1][0] = tmp[2]; bf[2 * np + 1][1] = tmp[3];
            }
            #pragma unroll
            for (int mi = 0; mi < 4; mi++)
                #pragma unroll
                for (int ni = 0; ni < 4; ni++)
                    mma_fp8(c[mi][ni], af[mi], bf[ni]);
        }
        __syncthreads();
    }

    // Epilogue: (acc/16) + bias, interleaved RoPE, write e4m3 q/k.
    const float L2C = -13.287712379549449f / 32.0f;  // -log2(10000)/32
    #pragma unroll
    for (int mi = 0; mi < 4; mi++) {
        #pragma unroll
        for (int ni = 0; ni < 4; ni++) {
            const int row0 = m0 + wm * 64 + mi * 16 + g;
            const int n = n0 + wn * 32 + ni * 8 + 2 * tg;
            const int ent = n >> 7, j = n & 127;
            const int isK = j >> 6, d = j & 63, fi = d >> 1;
            const float inv = exp2f((float)fi * L2C);
            const float b0v = bias[n], b1v = bias[n + 1];
            const float x00 = c[mi][ni][0] * INV_W_SCALE + b0v;
            const float x01 = c[mi][ni][1] * INV_W_SCALE + b1v;
            const float x10 = c[mi][ni][2] * INV_W_SCALE + b0v;
            const float x11 = c[mi][ni][3] * INV_W_SCALE + b1v;
            const int bb = row0 >> 9, s0 = row0 & 511;
            float sn0, cs0, sn1, cs1;
            __sincosf((float)s0 * inv, &sn0, &cs0);
            __sincosf((float)(s0 + 8) * inv, &sn1, &cs1);
            const float y00 = x00 * cs0 - x01 * sn0, y01 = x01 * cs0 + x00 * sn0;
            const float y10 = x10 * cs1 - x11 * sn1, y11 = x11 * cs1 + x10 * sn1;
            uint8_t* p = isK ? g_k8 : g_q8;
            const size_t base = (((size_t)(bb * 9 + ent)) * 512 + s0) * 64 + d;
            *(uint16_t*)&p[base]           = pack_e4m3x2(y01, y00);
            *(uint16_t*)&p[base + 8 * 64]  = pack_e4m3x2(y11, y10);
        }
    }
}

// ---------------- Kernel B: QK^T (fp8 mma.sync) + masks ----------------
// Tile 64(m) x 128(n), 8 warps (2m x 4n), warp tile 32x32, K=64 (2 k-steps).
__global__ __launch_bounds__(256, 3) void attn_mma_kernel(const float* __restrict__ amask,
                                                          float* __restrict__ out)
{
    const int S = 80;
    __shared__ __align__(16) uint8_t Qs[64 * 80];
    __shared__ __align__(16) uint8_t Ks[128 * 80];

    const int t = threadIdx.x, lane = t & 31, wid = t >> 5;
    const int wm = wid >> 2, wn = wid & 3;
    const int g = lane >> 2, tg = lane & 3;
    const int qd = lane >> 3, rr8 = lane & 7;
    const int a_r = (qd & 1) * 8 + rr8, a_c = (qd >> 1) * 16;
    const int b_r = (qd >> 1) * 8 + rr8, b_c = (qd & 1) * 16;

    const int tn = blockIdx.x, tm = blockIdx.y, bh = blockIdx.z;
    const int b = bh / 9;
    const int m0 = tm * 64, n0 = tn * 128;

    if (2 * (tn + 1) <= tm) {  // fully causal-masked: constant output
        const int cg = (t & 31) * 4, rbase = t >> 5;
        float4 v;
        #pragma unroll
        for (int ci = 0; ci < 4; ci++) {
            float pad = amask[b * 512 + n0 + cg + ci];
            ((float*)&v)[ci] = (-(1.0f - pad) * NEG_INF_F - NEG_INF_F) * 0.125f;
        }
        #pragma unroll
        for (int rp = 0; rp < 8; rp++) {
            int m = m0 + rbase + rp * 8;
            *(float4*)&out[((size_t)bh * 512 + m) * 512 + n0 + cg] = v;
        }
        return;
    }

    const size_t qbase = (size_t)bh * 512 * 64;
    {   // Q: 64 rows x 64B = 256 chunks (1/thread)
        const int row = t >> 2, cc = (t & 3) * 16;
        *(uint4*)&Qs[row * S + cc] = *(const uint4*)&g_q8[qbase + (size_t)(m0 + row) * 64 + cc];
    }
    #pragma unroll
    for (int p = 0; p < 2; p++) {   // K: 128 rows = 512 chunks (2/thread)
        const int idx = p * 256 + t;
        const int row = idx >> 2, cc = (idx & 3) * 16;
        *(uint4*)&Ks[row * S + cc] = *(const uint4*)&g_k8[qbase + (size_t)(n0 + row) * 64 + cc];
    }
    __syncthreads();

    float c[2][4][4];
    #pragma unroll
    for (int i = 0; i < 2; i++)
        #pragma unroll
        for (int j = 0; j < 4; j++)
            #pragma unroll
            for (int k = 0; k < 4; k++) c[i][j][k] = 0.f;

    const uint32_t sQ = smem_u32(Qs), sK = smem_u32(Ks);

    #pragma unroll
    for (int ks = 0; ks < 2; ks++) {
        uint32_t af[2][4];
        #pragma unroll
        for (int mi = 0; mi < 2; mi++)
            ldm_x4(af[mi], sQ + (wm * 32 + mi * 16 + a_r) * S + ks * 32 + a_c);
        uint32_t bf[4][2];
        #pragma unroll
        for (int np = 0; np < 2; np++) {
            uint32_t tmp[4];
            ldm_x4(tmp, sK + (wn * 32 + np * 16 + b_r) * S + ks * 32 + b_c);
            bf[2 * np][0] = tmp[0]; bf[2 * np][1] = tmp[1];
            bf[2 * np + 1][0] = tmp[2]; bf[2 * np + 1][1] = tmp[3];
        }
        #pragma unroll
        for (int mi = 0; mi < 2; mi++)
            #pragma unroll
            for (int ni = 0; ni < 4; ni++)
                mma_fp8(c[mi][ni], af[mi], bf[ni]);
    }

    // Epilogue: pad mask, strict-lower causal, scale 1/8.
    #pragma unroll
    for (int mi = 0; mi < 2; mi++) {
        #pragma unroll
        for (int ni = 0; ni < 4; ni++) {
            const int row0 = m0 + wm * 32 + mi * 16 + g;
            const int row1 = row0 + 8;
            const int n = n0 + wn * 32 + ni * 8 + 2 * tg;
            const float pad0 = amask[b * 512 + n];
            const float pad1 = amask[b * 512 + n + 1];
            const float* cc = c[mi][ni];
            float v00 = cc[0] * pad0 - (1.f - pad0) * NEG_INF_F - (n     < row0 ? NEG_INF_F : 0.f);
            float v01 = cc[1] * pad1 - (1.f - pad1) * NEG_INF_F - (n + 1 < row0 ? NEG_INF_F : 0.f);
            float v10 = cc[2] * pad0 - (1.f - pad0) * NEG_INF_F - (n     < row1 ? NEG_INF_F : 0.f);
            float v11 = cc[3] * pad1 - (1.f - pad1) * NEG_INF_F - (n + 1 < row1 ? NEG_INF_F : 0.f);
            float2 o0 = {v00 * 0.125f, v01 * 0.125f};
            float2 o1 = {v10 * 0.125f, v11 * 0.125f};
            *(float2*)&out[((size_t)bh * 512 + row0) * 512 + n] = o0;
            *(float2*)&out[((size_t)bh * 512 + row1) * 512 + n] = o1;
        }
    }
}

// ---------------- launch ----------------
extern "C" void kernel_launch(void* const* d_in, const int* in_sizes, int n_in,
                              void* d_out, int out_size)
{
    const float* X    = (const float*)d_in[0];
    const float* amsk = (const float*)d_in[1];
    const float* W    = (const float*)d_in[2];
    const float* bias = (const float*)d_in[3];
    float* out = (float*)d_out;
    (void)in_sizes; (void)n_in; (void)out_size;

    conv_X_kernel<<<1024, 256>>>(X);
    {
        dim3 grid(36, 24);       // n-tiles, k-tiles
        conv_WT_kernel<<<grid, 256>>>(W);
    }
    {
        dim3 grid(9, 64);        // N/128, M/128
        proj_mma_kernel<<<grid, 256>>>(bias);
    }
    {
        dim3 grid(4, 8, 144);    // n-tiles(128), m-tiles(64), b*h
        attn_mma_kernel<<<grid, 256>>>(amsk, out);
    }
}